// round 3
// baseline (speedup 1.0000x reference)
#include <cuda_runtime.h>
#include <cstdint>
#include <math.h>

// CapsuleLayer collapses (b never updates across routing iters) to:
//   out = squash_z1( r(h,w) * denseconv5x5(x[4,64,128,128], W[128,64,5,5], pad=2) )
//   r(h,w) = 1 / (8 * cntH(h) * cntW(w)),  cnt = valid pixels of 5x5 window
// Implemented as tf32 mma.sync implicit GEMM (legacy tensor path: the GPU-side
// toolchain targets plain sm_103 where tcgen05.ld/wait are unavailable).

// ------------------------- device scratch -------------------------
__device__ float g_Xp[4 * 128 * 128 * 64];   // NHWC, tf32-rounded (16 MB)
__device__ float g_Wp[25 * 64 * 128];        // [off][ci][oc], tf32-rounded

__device__ __forceinline__ float tf32_rna(float x) {
    uint32_t r;
    asm("cvt.rna.tf32.f32 %0, %1;" : "=r"(r) : "f"(x));
    return __uint_as_float(r);
}

__device__ __forceinline__ uint32_t smem_u32(const void* p) {
    uint32_t a;
    asm("{ .reg .u64 t; cvta.to.shared.u64 t, %1; cvt.u32.u64 %0, t; }"
        : "=r"(a) : "l"(p));
    return a;
}

__device__ __forceinline__ void cp_async16(uint32_t dst, const void* src, uint32_t src_sz) {
    asm volatile("cp.async.cg.shared.global [%0], [%1], 16, %2;"
                 :: "r"(dst), "l"(src), "r"(src_sz) : "memory");
}
__device__ __forceinline__ void cp_commit() {
    asm volatile("cp.async.commit_group;" ::: "memory");
}
template <int N>
__device__ __forceinline__ void cp_wait() {
    asm volatile("cp.async.wait_group %0;" :: "n"(N) : "memory");
}

__device__ __forceinline__ void mma_tf32(float& d0, float& d1, float& d2, float& d3,
                                         uint32_t a0, uint32_t a1, uint32_t a2, uint32_t a3,
                                         uint32_t b0, uint32_t b1) {
    asm volatile(
        "mma.sync.aligned.m16n8k8.row.col.f32.tf32.tf32.f32 "
        "{%0,%1,%2,%3}, {%4,%5,%6,%7}, {%8,%9}, {%0,%1,%2,%3};"
        : "+f"(d0), "+f"(d1), "+f"(d2), "+f"(d3)
        : "r"(a0), "r"(a1), "r"(a2), "r"(a3), "r"(b0), "r"(b1));
}

// ------------------------- prep kernels -------------------------
// u: [4, 64, 128, 128] NCHW  ->  g_Xp: [4, 128, 128, 64] NHWC (tf32-rounded)
__global__ void prep_x_kernel(const float* __restrict__ u) {
    __shared__ float tile[64][33];
    int blk = blockIdx.x;                 // 2048 blocks
    int wt = blk & 3;
    int h = (blk >> 2) & 127;
    int n = blk >> 9;
    int tid = threadIdx.x;                // 256
    int lw = tid & 31, lc = tid >> 5;
#pragma unroll
    for (int r = 0; r < 8; ++r) {
        int c = r * 8 + lc;
        float v = u[(((n << 6) + c) << 14) + (h << 7) + (wt << 5) + lw];
        tile[c][lw] = tf32_rna(v);
    }
    __syncthreads();
    int cc = tid & 63, lw2 = tid >> 6;
#pragma unroll
    for (int r = 0; r < 8; ++r) {
        int wl = r * 4 + lw2;
        int w = (wt << 5) + wl;
        g_Xp[((((n << 7) + h) << 7) + w) * 64 + cc] = tile[cc][wl];
    }
}

// W: [4, 128, 16, 5, 5] -> g_Wp[(off*64 + ci)*128 + oc], ci = t0*16+z0
__global__ void prep_w_kernel(const float* __restrict__ W) {
    int idx = blockIdx.x * 256 + threadIdx.x;   // 204800 total
    int oc  = idx & 127;
    int ci  = (idx >> 7) & 63;
    int off = idx >> 13;
    int t0 = ci >> 4, z0 = ci & 15;
    g_Wp[idx] = tf32_rna(W[((t0 * 128 + oc) * 16 + z0) * 25 + off]);
}

// ------------------------- main GEMM kernel -------------------------
// Grid: 256 CTAs. CTA = (n = b>>6, h0 = (b&63)*2). M=256 pixels (2 rows x 128 w),
// N=128 oc, K = 50 stages of 32 (25 offsets x 2 ci-chunks).
// 512 threads = 16 warps in 4x4 grid, warp tile 64x32.

static constexpr int A_PITCH = 36;    // floats per pixel row in smem (pad for banks)
static constexpr int B_PITCH = 136;   // floats per ci row in smem
static constexpr int A_STAGE = 256 * A_PITCH;          // 9216 floats
static constexpr int B_STAGE = 32 * B_PITCH;           // 4352 floats
static constexpr uint32_t SMEM_BYTES = (2 * A_STAGE + 2 * B_STAGE) * 4;  // 108544

__global__ void __launch_bounds__(512, 1) conv_main_kernel(float* __restrict__ out) {
    extern __shared__ float smem[];
    float* As[2] = { smem, smem + A_STAGE };
    float* Bs[2] = { smem + 2 * A_STAGE, smem + 2 * A_STAGE + B_STAGE };
    uint32_t smem_base = smem_u32(smem);

    int tid = threadIdx.x;
    int lane = tid & 31;
    int wid = tid >> 5;
    int wm = wid >> 2, wn = wid & 3;
    int b = blockIdx.x;
    int n = b >> 6;
    int h0 = (b & 63) << 1;

    float acc[4][4][4];
#pragma unroll
    for (int i = 0; i < 4; ++i)
#pragma unroll
        for (int j = 0; j < 4; ++j)
#pragma unroll
            for (int k = 0; k < 4; ++k) acc[i][j][k] = 0.f;

    // ---- stage loader: s -> (ky, chunk, kx), double-buffered cp.async ----
    auto load_stage = [&](int s) {
        int buf = s & 1;
        int ky = s / 10;
        int rem = s - ky * 10;
        int chunk = rem / 5;
        int kx = rem - chunk * 5;
        int off = ky * 5 + kx;
        uint32_t aB = smem_base + (uint32_t)buf * (A_STAGE * 4);
        uint32_t bB = smem_base + (uint32_t)(2 * A_STAGE + buf * B_STAGE) * 4;
        // A: 256 pixels x 32 ci = 2048 x 16B, 4 per thread
#pragma unroll
        for (int i = 0; i < 4; ++i) {
            int idx = tid + i * 512;
            int m = idx >> 3, seg = idx & 7;
            int r = m >> 7, w = m & 127;
            int hh = h0 + r + ky - 2;
            int ww = w + kx - 2;
            const float* src = g_Xp + ((((n << 7) + hh) << 7) + ww) * 64 + chunk * 32 + seg * 4;
            uint32_t ok = ((unsigned)hh < 128u && (unsigned)ww < 128u) ? 16u : 0u;
            cp_async16(aB + (uint32_t)(m * (A_PITCH * 4) + seg * 16), src, ok);
        }
        // B: 32 ci x 128 oc = 1024 x 16B, 2 per thread
#pragma unroll
        for (int i = 0; i < 2; ++i) {
            int idx = tid + i * 512;
            int ci = idx >> 5, ocb = idx & 31;
            const float* src = g_Wp + ((off * 64 + chunk * 32 + ci) << 7) + ocb * 4;
            cp_async16(bB + (uint32_t)(ci * (B_PITCH * 4) + ocb * 16), src, 16u);
        }
        cp_commit();
    };

    load_stage(0);

    const int m_base = wm * 64 + (lane >> 2);
    const int oc_base = wn * 32 + (lane >> 2);
    const int tg = lane & 3;

    for (int s = 0; s < 50; ++s) {
        if (s + 1 < 50) {
            load_stage(s + 1);
            cp_wait<1>();
        } else {
            cp_wait<0>();
        }
        __syncthreads();

        const float* A = As[s & 1];
        const float* B = Bs[s & 1];
#pragma unroll
        for (int ks = 0; ks < 4; ++ks) {
            uint32_t af[4][4], bf[4][2];
#pragma unroll
            for (int mf = 0; mf < 4; ++mf) {
                const float* ap = A + (m_base + mf * 16) * A_PITCH + ks * 8 + tg;
                af[mf][0] = __float_as_uint(ap[0]);
                af[mf][1] = __float_as_uint(ap[8 * A_PITCH]);
                af[mf][2] = __float_as_uint(ap[4]);
                af[mf][3] = __float_as_uint(ap[8 * A_PITCH + 4]);
            }
#pragma unroll
            for (int nf = 0; nf < 4; ++nf) {
                const float* bp = B + (ks * 8 + tg) * B_PITCH + oc_base + nf * 8;
                bf[nf][0] = __float_as_uint(bp[0]);
                bf[nf][1] = __float_as_uint(bp[4 * B_PITCH]);
            }
#pragma unroll
            for (int mf = 0; mf < 4; ++mf)
#pragma unroll
                for (int nf = 0; nf < 4; ++nf)
                    mma_tf32(acc[mf][nf][0], acc[mf][nf][1], acc[mf][nf][2], acc[mf][nf][3],
                             af[mf][0], af[mf][1], af[mf][2], af[mf][3],
                             bf[nf][0], bf[nf][1]);
        }
        __syncthreads();
    }

    // ---- epilogue: r(h,w) scale + squash over z1 (16 cols) + store ----
#pragma unroll
    for (int mf = 0; mf < 4; ++mf) {
#pragma unroll
        for (int half = 0; half < 2; ++half) {
            int m = wm * 64 + mf * 16 + half * 8 + (lane >> 2);
            int h = h0 + (m >> 7);
            int w = m & 127;
            int cntH = min(h + 2, 127) - max(h - 2, 0) + 1;
            int cntW = min(w + 2, 127) - max(w - 2, 0) + 1;
            float rr = 1.f / (8.f * (float)(cntH * cntW));
#pragma unroll
            for (int grp = 0; grp < 2; ++grp) {
                float v0 = acc[mf][grp * 2][half * 2];
                float v1 = acc[mf][grp * 2][half * 2 + 1];
                float v2 = acc[mf][grp * 2 + 1][half * 2];
                float v3 = acc[mf][grp * 2 + 1][half * 2 + 1];
                float ssum = v0 * v0 + v1 * v1 + v2 * v2 + v3 * v3;
                ssum += __shfl_xor_sync(0xffffffffu, ssum, 1);
                ssum += __shfl_xor_sync(0xffffffffu, ssum, 2);
                float n2 = rr * rr * ssum;
                float sc = rr * n2 / ((1.f + n2) * sqrtf(n2 + 1e-9f));
                int t1 = wn * 2 + grp;
                int z0 = tg * 2;
                float* ob = out + (((n * 8 + t1) * 16) << 14) + (h << 7) + w;
                ob[(z0 + 0) << 14] = v0 * sc;
                ob[(z0 + 1) << 14] = v1 * sc;
                ob[(z0 + 8) << 14] = v2 * sc;
                ob[(z0 + 9) << 14] = v3 * sc;
            }
        }
    }
}

// ------------------------- launch -------------------------
extern "C" void kernel_launch(void* const* d_in, const int* in_sizes, int n_in,
                              void* d_out, int out_size) {
    const float* u = (const float*)d_in[0];   // [4,4,16,128,128]
    const float* W = (const float*)d_in[1];   // [4,128,16,5,5]
    float* out = (float*)d_out;               // [4,8,16,128,128]
    (void)in_sizes; (void)n_in; (void)out_size;

    cudaFuncSetAttribute(conv_main_kernel,
                         cudaFuncAttributeMaxDynamicSharedMemorySize, SMEM_BYTES);

    prep_x_kernel<<<2048, 256>>>(u);
    prep_w_kernel<<<800, 256>>>(W);
    conv_main_kernel<<<256, 512, SMEM_BYTES>>>(out);
}

// round 6
// speedup vs baseline: 1.2645x; 1.2645x over previous
#include <cuda_runtime.h>
#include <cstdint>
#include <math.h>

// CapsuleLayer collapses (b never updates across routing iters) to:
//   out = squash_z1( r(h,w) * denseconv5x5(x[4,64,128,128], W[128,64,5,5], pad=2) )
//   r(h,w) = 1 / (8 * cntH(h) * cntW(w)),  cnt = valid pixels of 5x5 window
// tf32 mma.sync implicit GEMM (legacy tensor path; tcgen05.ld unavailable on
// the harness's plain-sm_103 ptxas target).
// R4: 4-stage cp.async ring w/ prefetch depth 2, ONE barrier per K-stage,
//     merged prep kernel (2 launches/call so ncu -s 5 samples the GEMM).

// ------------------------- device scratch -------------------------
__device__ float g_Xp[4 * 128 * 128 * 64];   // NHWC, tf32-rounded (16 MB)
__device__ float g_Wp[25 * 64 * 128];        // [off][ci][oc], tf32-rounded

__device__ __forceinline__ float tf32_rna(float x) {
    uint32_t r;
    asm("cvt.rna.tf32.f32 %0, %1;" : "=r"(r) : "f"(x));
    return __uint_as_float(r);
}

__device__ __forceinline__ uint32_t smem_u32(const void* p) {
    uint32_t a;
    asm("{ .reg .u64 t; cvta.to.shared.u64 t, %1; cvt.u32.u64 %0, t; }"
        : "=r"(a) : "l"(p));
    return a;
}

__device__ __forceinline__ void cp_async16(uint32_t dst, const void* src, uint32_t src_sz) {
    asm volatile("cp.async.cg.shared.global [%0], [%1], 16, %2;"
                 :: "r"(dst), "l"(src), "r"(src_sz) : "memory");
}
__device__ __forceinline__ void cp_commit() {
    asm volatile("cp.async.commit_group;" ::: "memory");
}
template <int N>
__device__ __forceinline__ void cp_wait() {
    asm volatile("cp.async.wait_group %0;" :: "n"(N) : "memory");
}

__device__ __forceinline__ void mma_tf32(float& d0, float& d1, float& d2, float& d3,
                                         uint32_t a0, uint32_t a1, uint32_t a2, uint32_t a3,
                                         uint32_t b0, uint32_t b1) {
    asm volatile(
        "mma.sync.aligned.m16n8k8.row.col.f32.tf32.tf32.f32 "
        "{%0,%1,%2,%3}, {%4,%5,%6,%7}, {%8,%9}, {%0,%1,%2,%3};"
        : "+f"(d0), "+f"(d1), "+f"(d2), "+f"(d3)
        : "r"(a0), "r"(a1), "r"(a2), "r"(a3), "r"(b0), "r"(b1));
}

// ------------------------- merged prep kernel -------------------------
// blocks [0, 2048):   u [4,64,128,128] NCHW -> g_Xp [4,128,128,64] NHWC (tf32)
// blocks [2048, 2848): W [4,128,16,5,5]     -> g_Wp [(off*64+ci)*128+oc] (tf32)
__global__ void prep_kernel(const float* __restrict__ u, const float* __restrict__ W) {
    __shared__ float tile[64][33];
    int tid = threadIdx.x;                // 256
    if (blockIdx.x < 2048) {
        int blk = blockIdx.x;
        int wt = blk & 3;
        int h = (blk >> 2) & 127;
        int n = blk >> 9;
        int lw = tid & 31, lc = tid >> 5;
#pragma unroll
        for (int r = 0; r < 8; ++r) {
            int c = r * 8 + lc;
            float v = u[(((n << 6) + c) << 14) + (h << 7) + (wt << 5) + lw];
            tile[c][lw] = tf32_rna(v);
        }
        __syncthreads();
        int cc = tid & 63, lw2 = tid >> 6;
#pragma unroll
        for (int r = 0; r < 8; ++r) {
            int wl = r * 4 + lw2;
            int w = (wt << 5) + wl;
            g_Xp[((((n << 7) + h) << 7) + w) * 64 + cc] = tile[cc][wl];
        }
    } else {
        int idx = (blockIdx.x - 2048) * 256 + tid;   // 204800 total
        int oc  = idx & 127;
        int ci  = (idx >> 7) & 63;
        int off = idx >> 13;
        int t0 = ci >> 4, z0 = ci & 15;
        g_Wp[idx] = tf32_rna(W[((t0 * 128 + oc) * 16 + z0) * 25 + off]);
    }
}

// ------------------------- main GEMM kernel -------------------------
// Grid: 256 CTAs. CTA = (n = b>>6, h0 = (b&63)*2). M=256 pixels (2 rows x 128 w),
// N=128 oc, K = 50 stages of 32 (25 offsets x 2 ci-chunks).
// 512 threads = 16 warps in 4x4 grid, warp tile 64x32.
// 4-stage smem ring, cp.async prefetch depth 2, one __syncthreads per stage.

static constexpr int NSTAGES = 50;
static constexpr int RING = 4;
static constexpr int A_PITCH = 36;    // floats per pixel row in smem (bank-free)
static constexpr int B_PITCH = 136;   // floats per ci row in smem
static constexpr int A_STAGE = 256 * A_PITCH;          // 9216 floats (36 KB)
static constexpr int B_STAGE = 32 * B_PITCH;           // 4352 floats (17 KB)
static constexpr uint32_t SMEM_BYTES = (RING * A_STAGE + RING * B_STAGE) * 4;  // 217088

__global__ void __launch_bounds__(512, 1) conv_main_kernel(float* __restrict__ out) {
    extern __shared__ float smem[];
    uint32_t smem_base = smem_u32(smem);

    int tid = threadIdx.x;
    int lane = tid & 31;
    int wid = tid >> 5;
    int wm = wid >> 2, wn = wid & 3;
    int b = blockIdx.x;
    int n = b >> 6;
    int h0 = (b & 63) << 1;

    float acc[4][4][4];
#pragma unroll
    for (int i = 0; i < 4; ++i)
#pragma unroll
        for (int j = 0; j < 4; ++j)
#pragma unroll
            for (int k = 0; k < 4; ++k) acc[i][j][k] = 0.f;

    // ---- stage loader: s -> (ky, chunk, kx) ----
    auto load_stage = [&](int s) {
        int buf = s & (RING - 1);
        int ky = s / 10;
        int rem = s - ky * 10;
        int chunk = rem / 5;
        int kx = rem - chunk * 5;
        int off = ky * 5 + kx;
        uint32_t aB = smem_base + (uint32_t)buf * (A_STAGE * 4);
        uint32_t bB = smem_base + (uint32_t)(RING * A_STAGE + buf * B_STAGE) * 4;
        // A: 256 pixels x 32 ci = 2048 x 16B, 4 per thread
#pragma unroll
        for (int i = 0; i < 4; ++i) {
            int idx = tid + i * 512;
            int m = idx >> 3, seg = idx & 7;
            int r = m >> 7, w = m & 127;
            int hh = h0 + r + ky - 2;
            int ww = w + kx - 2;
            const float* src = g_Xp + ((((n << 7) + hh) << 7) + ww) * 64 + chunk * 32 + seg * 4;
            uint32_t ok = ((unsigned)hh < 128u && (unsigned)ww < 128u) ? 16u : 0u;
            cp_async16(aB + (uint32_t)(m * (A_PITCH * 4) + seg * 16), src, ok);
        }
        // B: 32 ci x 128 oc = 1024 x 16B, 2 per thread
#pragma unroll
        for (int i = 0; i < 2; ++i) {
            int idx = tid + i * 512;
            int ci = idx >> 5, ocb = idx & 31;
            const float* src = g_Wp + ((off * 64 + chunk * 32 + ci) << 7) + ocb * 4;
            cp_async16(bB + (uint32_t)(ci * (B_PITCH * 4) + ocb * 16), src, 16u);
        }
        cp_commit();
    };

    const int m_base = wm * 64 + (lane >> 2);
    const int oc_base = wn * 32 + (lane >> 2);
    const int tg = lane & 3;

    load_stage(0);
    load_stage(1);

    for (int s = 0; s < NSTAGES; ++s) {
        // Issue s+2 into ring slot (s+2)%4. Hazard vs compute(s-2) on the same
        // slot is covered by iteration s-1's barrier (program order: that warp
        // finished compute(s-2) before passing it).
        if (s + 2 < NSTAGES) {
            load_stage(s + 2);
            cp_wait<2>();      // stage s's group committed
        } else if (s + 1 < NSTAGES) {
            cp_wait<1>();
        } else {
            cp_wait<0>();
        }
        __syncthreads();       // stage s data visible to all warps

        const float* A = smem + (s & (RING - 1)) * A_STAGE;
        const float* B = smem + RING * A_STAGE + (s & (RING - 1)) * B_STAGE;
#pragma unroll
        for (int ks = 0; ks < 4; ++ks) {
            uint32_t af[4][4], bf[4][2];
#pragma unroll
            for (int mf = 0; mf < 4; ++mf) {
                const float* ap = A + (m_base + mf * 16) * A_PITCH + ks * 8 + tg;
                af[mf][0] = __float_as_uint(ap[0]);
                af[mf][1] = __float_as_uint(ap[8 * A_PITCH]);
                af[mf][2] = __float_as_uint(ap[4]);
                af[mf][3] = __float_as_uint(ap[8 * A_PITCH + 4]);
            }
#pragma unroll
            for (int nf = 0; nf < 4; ++nf) {
                const float* bp = B + (ks * 8 + tg) * B_PITCH + oc_base + nf * 8;
                bf[nf][0] = __float_as_uint(bp[0]);
                bf[nf][1] = __float_as_uint(bp[4 * B_PITCH]);
            }
#pragma unroll
            for (int mf = 0; mf < 4; ++mf)
#pragma unroll
                for (int nf = 0; nf < 4; ++nf)
                    mma_tf32(acc[mf][nf][0], acc[mf][nf][1], acc[mf][nf][2], acc[mf][nf][3],
                             af[mf][0], af[mf][1], af[mf][2], af[mf][3],
                             bf[nf][0], bf[nf][1]);
        }
    }

    // ---- epilogue: r(h,w) scale + squash over z1 (16 cols) + store ----
#pragma unroll
    for (int mf = 0; mf < 4; ++mf) {
#pragma unroll
        for (int half = 0; half < 2; ++half) {
            int m = wm * 64 + mf * 16 + half * 8 + (lane >> 2);
            int h = h0 + (m >> 7);
            int w = m & 127;
            int cntH = min(h + 2, 127) - max(h - 2, 0) + 1;
            int cntW = min(w + 2, 127) - max(w - 2, 0) + 1;
            float rr = 1.f / (8.f * (float)(cntH * cntW));
#pragma unroll
            for (int grp = 0; grp < 2; ++grp) {
                float v0 = acc[mf][grp * 2][half * 2];
                float v1 = acc[mf][grp * 2][half * 2 + 1];
                float v2 = acc[mf][grp * 2 + 1][half * 2];
                float v3 = acc[mf][grp * 2 + 1][half * 2 + 1];
                float ssum = v0 * v0 + v1 * v1 + v2 * v2 + v3 * v3;
                ssum += __shfl_xor_sync(0xffffffffu, ssum, 1);
                ssum += __shfl_xor_sync(0xffffffffu, ssum, 2);
                float n2 = rr * rr * ssum;
                float sc = rr * n2 / ((1.f + n2) * sqrtf(n2 + 1e-9f));
                int t1 = wn * 2 + grp;
                int z0 = tg * 2;
                float* ob = out + (((n * 8 + t1) * 16) << 14) + (h << 7) + w;
                ob[(z0 + 0) << 14] = v0 * sc;
                ob[(z0 + 1) << 14] = v1 * sc;
                ob[(z0 + 8) << 14] = v2 * sc;
                ob[(z0 + 9) << 14] = v3 * sc;
            }
        }
    }
}

// ------------------------- launch -------------------------
extern "C" void kernel_launch(void* const* d_in, const int* in_sizes, int n_in,
                              void* d_out, int out_size) {
    const float* u = (const float*)d_in[0];   // [4,4,16,128,128]
    const float* W = (const float*)d_in[1];   // [4,128,16,5,5]
    float* out = (float*)d_out;               // [4,8,16,128,128]
    (void)in_sizes; (void)n_in; (void)out_size;

    cudaFuncSetAttribute(conv_main_kernel,
                         cudaFuncAttributeMaxDynamicSharedMemorySize, SMEM_BYTES);

    prep_kernel<<<2848, 256>>>(u, W);
    conv_main_kernel<<<256, 512, SMEM_BYTES>>>(out);
}